// round 16
// baseline (speedup 1.0000x reference)
#include <cuda_runtime.h>
#include <cstdint>
#include <cstddef>
#include <math.h>

#define B_TOTAL 512
#define T_LEN   256
#define HID     128
#define G4      512
#define WINDOW  8
#define ENCO    128
#define R_ROWS  4
#define NCTA    128
#define NTHR    256
#define K4_SM   20           // k-quads in smem: k 0..79
#define TAIL_P  24           // k-pairs 40..63 (k 80..127) in registers, per column
#define BT      (B_TOTAL * T_LEN)

typedef unsigned long long ull;

__device__ __forceinline__ ull ffma2(ull a, ull b, ull c) {
    ull d;
    asm("fma.rn.f32x2 %0, %1, %2, %3;" : "=l"(d) : "l"(a), "l"(b), "l"(c));
    return d;
}
__device__ __forceinline__ float lo32(ull v) { return __uint_as_float((unsigned)v); }
__device__ __forceinline__ float hi32(ull v) { return __uint_as_float((unsigned)(v >> 32)); }
__device__ __forceinline__ ull pack2(float a, float b) {
    return (ull)__float_as_uint(a) | ((ull)__float_as_uint(b) << 32);
}
__device__ __forceinline__ float sigf(float x) {
    return __fdividef(1.f, 1.f + __expf(-x));
}
__device__ __forceinline__ float tanhf_(float x) {
    return 1.f - __fdividef(2.f, 1.f + __expf(2.f * x));
}

struct Smem {
    ull   Wq[K4_SM][G4][2];       // 163840 B : W_hh k0..79, 16B per (k4,col)
    alignas(16) ull h2[2][R_ROWS][HID/2];  // 4096 B : double-buffered h
    float gq[R_ROWS][HID][4];     //   8192 B : gates [row][unit][gate] (init staging too)
    float tout[R_ROWS][T_LEN];    //   4096 B
    float intv[R_ROWS][T_LEN];    //   4096 B
    float xv[R_ROWS][WINDOW][5];  //    640 B
    float fc1b[HID];              //    512 B
    float fc2w[HID];              //    512 B
    float Esm[R_ROWS];            //     16 B
    float red[R_ROWS][4];         //     64 B
};

// fc1 weights as transposed pairs
__device__ ull g_fc1p[64 * HID];

__global__ void prep_fc1(const float* __restrict__ fc1_w) {
    int idx = blockIdx.x * blockDim.x + threadIdx.x;
    if (idx < 64 * HID) {
        int k2 = idx >> 7, u = idx & 127;
        g_fc1p[idx] = pack2(fc1_w[u * HID + 2 * k2], fc1_w[u * HID + 2 * k2 + 1]);
    }
}

__global__ __launch_bounds__(NTHR, 1)
void modnn_kernel(const float* __restrict__ X,
                  const float* __restrict__ W_ih, const float* __restrict__ W_hh,
                  const float* __restrict__ b_ih, const float* __restrict__ b_hh,
                  const float* __restrict__ fc1_b,
                  const float* __restrict__ fc2_w, const float* __restrict__ fc2_b,
                  const float* __restrict__ int1_w, const float* __restrict__ int1_b,
                  const float* __restrict__ int3_w, const float* __restrict__ int3_b,
                  const float* __restrict__ scale_w, const float* __restrict__ zone_w,
                  float* __restrict__ out)
{
    extern __shared__ char smem_raw[];
    Smem* s = reinterpret_cast<Smem*>(smem_raw);
    const int tid  = threadIdx.x;
    const int b0   = blockIdx.x * R_ROWS;
    const int w    = tid >> 5;
    const int l    = tid & 31;
    const int half = l >> 4;                 // 0: gates (i,g); 1: gates (f,o)
    const int u    = w * 16 + (l & 15);      // my unit 0..127
    const int cA   = u + half * 128;         // gate col (i or f)
    const int cB   = cA + 256;               // gate col (g or o)

    // ---- stage W_hh k=0..79 as [k4][col] 16B quads ----
    for (int idx = tid; idx < K4_SM * G4; idx += NTHR) {
        int k4 = idx >> 9, col = idx & 511;
        const float* wr = W_hh + (size_t)col * HID + 4 * k4;
        s->Wq[k4][col][0] = pack2(wr[0], wr[1]);
        s->Wq[k4][col][1] = pack2(wr[2], wr[3]);
    }
    if (tid < HID) { s->fc1b[tid] = fc1_b[tid]; s->fc2w[tid] = fc2_w[tid]; }

    // stage int-module weights into gq area (reused later)
    {
        float* tmp = &s->gq[0][0][0];
        for (int idx = tid; idx < HID * 3; idx += NTHR) tmp[idx] = int1_w[idx];
        for (int idx = tid; idx < HID; idx += NTHR) {
            tmp[384 + idx] = int1_b[idx];
            tmp[512 + idx] = int3_w[idx];
        }
    }

    // ---- per-thread invariants in registers ----
    float wihA[5], wihB[5];
    #pragma unroll
    for (int j = 0; j < 5; ++j) {
        wihA[j] = W_ih[cA * 5 + j];
        wihB[j] = W_ih[cB * 5 + j];
    }
    const float btA = b_ih[cA] + b_hh[cA];
    const float btB = b_ih[cB] + b_hh[cB];

    // ---- W_hh tail (k 80..127 = pairs 40..63) in registers, 2 columns ----
    ull wt0[TAIL_P], wt1[TAIL_P];
    {
        const ull* p0 = reinterpret_cast<const ull*>(W_hh + (size_t)cA * HID + 80);
        const ull* p1 = reinterpret_cast<const ull*>(W_hh + (size_t)cB * HID + 80);
        #pragma unroll
        for (int j = 0; j < TAIL_P; ++j) { wt0[j] = p0[j]; wt1[j] = p1[j]; }
    }

    const float zone = zone_w[0];
    const float fcb2 = fc2_b[0];
    const float i3b  = int3_b[0];
    const float scl  = scale_w[0];
    __syncthreads();

    // ---- precompute int_all; emit constant outputs; init tout/h/Esm ----
    {
        const float* tmp = &s->gq[0][0][0];
        for (int it = tid; it < R_ROWS * T_LEN; it += NTHR) {
            int r = it >> 8, tt = it & 255;
            const float* Xb = X + (size_t)(b0 + r) * (T_LEN * 7) + tt * 7;
            float x0 = Xb[3], x1 = Xb[4], x2 = Xb[5];
            float acc = 0.f;
            #pragma unroll 8
            for (int uu = 0; uu < HID; ++uu) {
                float v = fmaf(tmp[uu*3], x0, fmaf(tmp[uu*3+1], x1, fmaf(tmp[uu*3+2], x2, tmp[384+uu])));
                v = fmaxf(v, 0.f);
                acc = fmaf(v, tmp[512 + uu], acc);
            }
            float val = scl * (1.f / (1.f + expf(-(acc + i3b))));
            s->intv[r][tt] = val;
            size_t base = (size_t)(b0 + r) * T_LEN + tt;
            out[(size_t)BT + base]   = Xb[6];                          // HVAC_list
            out[3*(size_t)BT + base] = (tt >= WINDOW) ? val : 0.f;     // Int_list
            if (tt < WINDOW) {
                out[base]                = Xb[0];                      // TOut[:, :w]
                out[2*(size_t)BT + base] = 0.f;                        // Ext zeros
                s->tout[r][tt] = Xb[0];
            }
        }
        if (tid < R_ROWS)
            s->Esm[tid] = X[(size_t)(b0 + tid) * (T_LEN * 7) + WINDOW * 7];
    }
    __syncthreads();   // staging reads done before h init / gq reuse
    for (int idx = tid; idx < R_ROWS * (HID/2); idx += NTHR)
        s->h2[0][idx >> 6][idx & 63] = pack2(1.f, 1.f);
    float c0 = 1.f, c1 = 1.f;   // cell states for rows half, half+2 of unit u
    __syncthreads();

    // ================= main sequential time loop =================
    for (int i = WINDOW; i < T_LEN; ++i) {
        const bool  enc   = (i < ENCO);
        const float ratio = enc ? (float)i * (1.f / ENCO) : 0.f;

        // ---- window build ----
        if (tid < R_ROWS * WINDOW) {
            int r = tid >> 3, tt = tid & 7;
            int pos = i - (WINDOW - 1) + tt;
            const float* Xb = X + (size_t)(b0 + r) * (T_LEN * 7);
            float TO;
            if (tt == WINDOW - 1) {
                TO = s->Esm[r];
                s->tout[r][i] = TO;
                out[(size_t)(b0 + r) * T_LEN + i] = TO;
            } else {
                TO = s->tout[r][pos];
            }
            float e0 = enc ? fmaf(Xb[pos * 7], ratio, TO * (1.f - ratio)) : TO;
            s->xv[r][tt][0] = e0;
            #pragma unroll
            for (int j = 1; j < 5; ++j) s->xv[r][tt][j] = Xb[pos * 7 + j];
        }
        __syncthreads();

        // ---- 8 LSTM sub-steps, ONE CTA barrier each ----
        #pragma unroll 1
        for (int st = 0; st < WINDOW; ++st) {
            const int pb = st & 1;
            ull a00 = 0, a01 = 0, a02 = 0, a03 = 0;
            ull a10 = 0, a11 = 0, a12 = 0, a13 = 0;
            const ulonglong2* hq0 = reinterpret_cast<const ulonglong2*>(s->h2[pb][0]);
            const ulonglong2* hq1 = reinterpret_cast<const ulonglong2*>(s->h2[pb][1]);
            const ulonglong2* hq2 = reinterpret_cast<const ulonglong2*>(s->h2[pb][2]);
            const ulonglong2* hq3 = reinterpret_cast<const ulonglong2*>(s->h2[pb][3]);
            // smem part: k-quads 0..19 (k 0..79)
            #pragma unroll 5
            for (int k4 = 0; k4 < K4_SM; ++k4) {
                ulonglong2 w0 = *reinterpret_cast<const ulonglong2*>(&s->Wq[k4][cA][0]);
                ulonglong2 w1 = *reinterpret_cast<const ulonglong2*>(&s->Wq[k4][cB][0]);
                ulonglong2 h0 = hq0[k4], h1 = hq1[k4], h2 = hq2[k4], h3 = hq3[k4];
                a00 = ffma2(w0.x, h0.x, a00);  a00 = ffma2(w0.y, h0.y, a00);
                a10 = ffma2(w1.x, h0.x, a10);  a10 = ffma2(w1.y, h0.y, a10);
                a01 = ffma2(w0.x, h1.x, a01);  a01 = ffma2(w0.y, h1.y, a01);
                a11 = ffma2(w1.x, h1.x, a11);  a11 = ffma2(w1.y, h1.y, a11);
                a02 = ffma2(w0.x, h2.x, a02);  a02 = ffma2(w0.y, h2.y, a02);
                a12 = ffma2(w1.x, h2.x, a12);  a12 = ffma2(w1.y, h2.y, a12);
                a03 = ffma2(w0.x, h3.x, a03);  a03 = ffma2(w0.y, h3.y, a03);
                a13 = ffma2(w1.x, h3.x, a13);  a13 = ffma2(w1.y, h3.y, a13);
            }
            // register tail: FULLY UNROLLED so wt0/wt1 stay in registers
            #pragma unroll
            for (int q = 0; q < TAIL_P / 2; ++q) {
                ulonglong2 h0 = hq0[K4_SM + q], h1 = hq1[K4_SM + q];
                ulonglong2 h2 = hq2[K4_SM + q], h3 = hq3[K4_SM + q];
                ull wa0 = wt0[2*q], wb0 = wt0[2*q+1];
                ull wa1 = wt1[2*q], wb1 = wt1[2*q+1];
                a00 = ffma2(wa0, h0.x, a00);  a00 = ffma2(wb0, h0.y, a00);
                a10 = ffma2(wa1, h0.x, a10);  a10 = ffma2(wb1, h0.y, a10);
                a01 = ffma2(wa0, h1.x, a01);  a01 = ffma2(wb0, h1.y, a01);
                a11 = ffma2(wa1, h1.x, a11);  a11 = ffma2(wb1, h1.y, a11);
                a02 = ffma2(wa0, h2.x, a02);  a02 = ffma2(wb0, h2.y, a02);
                a12 = ffma2(wa1, h2.x, a12);  a12 = ffma2(wb1, h2.y, a12);
                a03 = ffma2(wa0, h3.x, a03);  a03 = ffma2(wb0, h3.y, a03);
                a13 = ffma2(wa1, h3.x, a13);  a13 = ffma2(wb1, h3.y, a13);
            }
            // x-part computed AFTER the dot (short live ranges)
            float init0[R_ROWS], init1[R_ROWS];
            #pragma unroll
            for (int r = 0; r < R_ROWS; ++r) {
                float v0 = btA, v1 = btB;
                #pragma unroll
                for (int j = 0; j < 5; ++j) {
                    float xj = s->xv[r][st][j];
                    v0 = fmaf(xj, wihA[j], v0);
                    v1 = fmaf(xj, wihB[j], v1);
                }
                init0[r] = v0; init1[r] = v1;
            }
            // gate store: [row][unit][gate]; my gates are 'half' and 'half+2'
            s->gq[0][u][half]     = init0[0] + lo32(a00) + hi32(a00);
            s->gq[1][u][half]     = init0[1] + lo32(a01) + hi32(a01);
            s->gq[2][u][half]     = init0[2] + lo32(a02) + hi32(a02);
            s->gq[3][u][half]     = init0[3] + lo32(a03) + hi32(a03);
            s->gq[0][u][half + 2] = init1[0] + lo32(a10) + hi32(a10);
            s->gq[1][u][half + 2] = init1[1] + lo32(a11) + hi32(a11);
            s->gq[2][u][half + 2] = init1[2] + lo32(a12) + hi32(a12);
            s->gq[3][u][half + 2] = init1[3] + lo32(a13) + hi32(a13);
            __syncwarp();   // all 4 gates of my warp's units ready (warp-local)

            // phase 2: rows 'half' and 'half+2' of unit u (warp-local g reads)
            {
                float* hf = reinterpret_cast<float*>(&s->h2[pb ^ 1][0][0]);
                {
                    int r = half;
                    float4 ga = *reinterpret_cast<const float4*>(&s->gq[r][u][0]);
                    c0 = sigf(ga.y) * c0 + sigf(ga.x) * tanhf_(ga.z);
                    hf[r * HID + u] = sigf(ga.w) * tanhf_(c0);
                }
                {
                    int r = half + 2;
                    float4 ga = *reinterpret_cast<const float4*>(&s->gq[r][u][0]);
                    c1 = sigf(ga.y) * c1 + sigf(ga.x) * tanhf_(ga.z);
                    hf[r * HID + u] = sigf(ga.w) * tanhf_(c1);
                }
            }
            __syncthreads();   // h[pb^1] complete before next sub-step's dot
        }

        // ---- ext head (final h is in buffer 0) ----
        {
            const int rA = tid >> 7;
            const int uu = tid & 127;
            const ull* hA = s->h2[0][rA];
            const ull* hB = s->h2[0][rA + 2];
            ull A0 = 0, A1 = 0;
            #pragma unroll 8
            for (int k2 = 0; k2 < 64; ++k2) {
                ull wv = __ldg(&g_fc1p[k2 * HID + uu]);
                A0 = ffma2(wv, hA[k2], A0);
                A1 = ffma2(wv, hB[k2], A1);
            }
            float b1 = s->fc1b[uu], w2 = s->fc2w[uu];
            float p0 = fmaxf(lo32(A0) + hi32(A0) + b1, 0.f) * w2;
            float p1 = fmaxf(lo32(A1) + hi32(A1) + b1, 0.f) * w2;
            #pragma unroll
            for (int m = 16; m > 0; m >>= 1) {
                p0 += __shfl_xor_sync(0xFFFFFFFFu, p0, m);
                p1 += __shfl_xor_sync(0xFFFFFFFFu, p1, m);
            }
            if ((tid & 31) == 0) {
                int w8 = tid >> 5;
                s->red[rA][w8 & 3]     = p0;
                s->red[rA + 2][w8 & 3] = p1;
            }
        }
        __syncthreads();

        // ---- scalar tail ----
        if (tid < R_ROWS) {
            int r = tid;
            float dot = s->red[r][0] + s->red[r][1] + s->red[r][2] + s->red[r][3];
            float ext = dot + fcb2;
            const float* Xb = X + (size_t)(b0 + r) * (T_LEN * 7);
            float hv = Xb[i * 7 + 6];
            float it = s->intv[r][i];
            float total = ext + hv + it;
            out[2*(size_t)BT + (size_t)(b0 + r) * T_LEN + i] = ext;
            float E = s->Esm[r];
            if (enc) E = ratio * Xb[i * 7] + (1.f - ratio) * E + total * zone;
            else     E = total * zone + E;
            s->Esm[r] = E;
        }
        __syncthreads();
    }
}

extern "C" void kernel_launch(void* const* d_in, const int* in_sizes, int n_in,
                              void* d_out, int out_size) {
    const float* X       = (const float*)d_in[0];
    const float* W_ih    = (const float*)d_in[1];
    const float* W_hh    = (const float*)d_in[2];
    const float* b_ih    = (const float*)d_in[3];
    const float* b_hh    = (const float*)d_in[4];
    const float* fc1_w   = (const float*)d_in[5];
    const float* fc1_b   = (const float*)d_in[6];
    const float* fc2_w   = (const float*)d_in[7];
    const float* fc2_b   = (const float*)d_in[8];
    const float* int1_w  = (const float*)d_in[9];
    const float* int1_b  = (const float*)d_in[10];
    const float* int3_w  = (const float*)d_in[11];
    const float* int3_b  = (const float*)d_in[12];
    const float* scale_w = (const float*)d_in[13];
    const float* zone_w  = (const float*)d_in[14];
    float* out = (float*)d_out;

    prep_fc1<<<64, 128>>>(fc1_w);

    size_t smem = sizeof(Smem);
    cudaFuncSetAttribute(modnn_kernel, cudaFuncAttributeMaxDynamicSharedMemorySize, (int)smem);
    modnn_kernel<<<NCTA, NTHR, smem>>>(X, W_ih, W_hh, b_ih, b_hh,
                                       fc1_b, fc2_w, fc2_b,
                                       int1_w, int1_b, int3_w, int3_b,
                                       scale_w, zone_w, out);
}

// round 17
// speedup vs baseline: 1.1026x; 1.1026x over previous
#include <cuda_runtime.h>
#include <cstdint>
#include <cstddef>
#include <math.h>

#define B_TOTAL 512
#define T_LEN   256
#define HID     128
#define G4      512
#define WINDOW  8
#define ENCO    128
#define R_ROWS  4
#define NCTA    128
#define NTHR    256
#define K4_SM   20           // k-quads in smem: k 0..79
#define TAIL_P  24           // k-pairs 40..63 (k 80..127) in registers, per column
#define BT      (B_TOTAL * T_LEN)

typedef unsigned long long ull;

__device__ __forceinline__ ull ffma2(ull a, ull b, ull c) {
    ull d;
    asm("fma.rn.f32x2 %0, %1, %2, %3;" : "=l"(d) : "l"(a), "l"(b), "l"(c));
    return d;
}
__device__ __forceinline__ float lo32(ull v) { return __uint_as_float((unsigned)v); }
__device__ __forceinline__ float hi32(ull v) { return __uint_as_float((unsigned)(v >> 32)); }
__device__ __forceinline__ ull pack2(float a, float b) {
    return (ull)__float_as_uint(a) | ((ull)__float_as_uint(b) << 32);
}
// hardware tanh (MUFU.TANH, base ISA since sm_75)
__device__ __forceinline__ float tanh_hw(float x) {
    float y;
    asm("tanh.approx.f32 %0, %1;" : "=f"(y) : "f"(x));
    return y;
}
__device__ __forceinline__ float sigf(float x) {
    return fmaf(0.5f, tanh_hw(0.5f * x), 0.5f);
}

struct Smem {
    ull   Wq[K4_SM][G4][2];       // 163840 B : W_hh k0..79, 16B per (k4,col)
    alignas(16) ull h2[R_ROWS][HID/2];  // 2048 B : hidden state packed pairs
    float g[R_ROWS][G4];          //   8192 B : gate pre-activations (init staging too)
    float tout[R_ROWS][T_LEN];    //   4096 B
    float intv[R_ROWS][T_LEN];    //   4096 B
    float xv[R_ROWS][WINDOW][5];  //    640 B
    float fc1b[HID];              //    512 B
    float fc2w[HID];              //    512 B
    float Esm[R_ROWS];            //     16 B
    float red[R_ROWS][4];         //     64 B
};

// fc1 weights as transposed pairs
__device__ ull g_fc1p[64 * HID];

__global__ void prep_fc1(const float* __restrict__ fc1_w) {
    int idx = blockIdx.x * blockDim.x + threadIdx.x;
    if (idx < 64 * HID) {
        int k2 = idx >> 7, u = idx & 127;
        g_fc1p[idx] = pack2(fc1_w[u * HID + 2 * k2], fc1_w[u * HID + 2 * k2 + 1]);
    }
}

__global__ __launch_bounds__(NTHR, 1)
void modnn_kernel(const float* __restrict__ X,
                  const float* __restrict__ W_ih, const float* __restrict__ W_hh,
                  const float* __restrict__ b_ih, const float* __restrict__ b_hh,
                  const float* __restrict__ fc1_b,
                  const float* __restrict__ fc2_w, const float* __restrict__ fc2_b,
                  const float* __restrict__ int1_w, const float* __restrict__ int1_b,
                  const float* __restrict__ int3_w, const float* __restrict__ int3_b,
                  const float* __restrict__ scale_w, const float* __restrict__ zone_w,
                  float* __restrict__ out)
{
    extern __shared__ char smem_raw[];
    Smem* s = reinterpret_cast<Smem*>(smem_raw);
    const int tid = threadIdx.x;
    const int b0  = blockIdx.x * R_ROWS;

    // ---- stage W_hh k=0..79 as [k4][col] 16B quads ----
    for (int idx = tid; idx < K4_SM * G4; idx += NTHR) {
        int k4 = idx >> 9, col = idx & 511;
        const float* wr = W_hh + (size_t)col * HID + 4 * k4;
        s->Wq[k4][col][0] = pack2(wr[0], wr[1]);
        s->Wq[k4][col][1] = pack2(wr[2], wr[3]);
    }
    if (tid < HID) { s->fc1b[tid] = fc1_b[tid]; s->fc2w[tid] = fc2_w[tid]; }

    // stage int-module weights into g area (reused later)
    {
        float* tmp = &s->g[0][0];
        for (int idx = tid; idx < HID * 3; idx += NTHR) tmp[idx] = int1_w[idx];
        for (int idx = tid; idx < HID; idx += NTHR) {
            tmp[384 + idx] = int1_b[idx];
            tmp[512 + idx] = int3_w[idx];
        }
    }

    // ---- per-thread invariants in registers ----
    float wihA[5], wihB[5];
    #pragma unroll
    for (int j = 0; j < 5; ++j) {
        wihA[j] = W_ih[tid * 5 + j];
        wihB[j] = W_ih[(tid + 256) * 5 + j];
    }
    const float btA = b_ih[tid] + b_hh[tid];
    const float btB = b_ih[tid + 256] + b_hh[tid + 256];

    // ---- W_hh tail (k 80..127 = pairs 40..63) in registers, 2 columns ----
    ull wt0[TAIL_P], wt1[TAIL_P];
    {
        const ull* p0 = reinterpret_cast<const ull*>(W_hh + (size_t)tid * HID + 80);
        const ull* p1 = reinterpret_cast<const ull*>(W_hh + (size_t)(tid + 256) * HID + 80);
        #pragma unroll
        for (int j = 0; j < TAIL_P; ++j) { wt0[j] = p0[j]; wt1[j] = p1[j]; }
    }

    const float zone = zone_w[0];
    const float fcb2 = fc2_b[0];
    const float i3b  = int3_b[0];
    const float scl  = scale_w[0];
    __syncthreads();

    // ---- precompute int_all; emit constant outputs; init tout/h/Esm ----
    {
        const float* tmp = &s->g[0][0];
        for (int it = tid; it < R_ROWS * T_LEN; it += NTHR) {
            int r = it >> 8, tt = it & 255;
            const float* Xb = X + (size_t)(b0 + r) * (T_LEN * 7) + tt * 7;
            float x0 = Xb[3], x1 = Xb[4], x2 = Xb[5];
            float acc = 0.f;
            #pragma unroll 8
            for (int u = 0; u < HID; ++u) {
                float v = fmaf(tmp[u*3], x0, fmaf(tmp[u*3+1], x1, fmaf(tmp[u*3+2], x2, tmp[384+u])));
                v = fmaxf(v, 0.f);
                acc = fmaf(v, tmp[512 + u], acc);
            }
            float val = scl * (1.f / (1.f + expf(-(acc + i3b))));   // accurate path (once)
            s->intv[r][tt] = val;
            size_t base = (size_t)(b0 + r) * T_LEN + tt;
            out[(size_t)BT + base]   = Xb[6];                          // HVAC_list
            out[3*(size_t)BT + base] = (tt >= WINDOW) ? val : 0.f;     // Int_list
            if (tt < WINDOW) {
                out[base]                = Xb[0];                      // TOut[:, :w]
                out[2*(size_t)BT + base] = 0.f;                        // Ext zeros
                s->tout[r][tt] = Xb[0];
            }
        }
        for (int idx = tid; idx < R_ROWS * (HID/2); idx += NTHR)
            s->h2[idx >> 6][idx & 63] = pack2(1.f, 1.f);
        if (tid < R_ROWS)
            s->Esm[tid] = X[(size_t)(b0 + tid) * (T_LEN * 7) + WINDOW * 7];
    }
    float c0 = 1.f, c1 = 1.f;
    const int rA = tid >> 7;       // phase-2 / fc1 rows: rA and rA+2
    const int uu = tid & 127;
    __syncthreads();

    // ================= main sequential time loop =================
    for (int i = WINDOW; i < T_LEN; ++i) {
        const bool  enc   = (i < ENCO);
        const float ratio = enc ? (float)i * (1.f / ENCO) : 0.f;

        // ---- window build ----
        if (tid < R_ROWS * WINDOW) {
            int r = tid >> 3, tt = tid & 7;
            int pos = i - (WINDOW - 1) + tt;
            const float* Xb = X + (size_t)(b0 + r) * (T_LEN * 7);
            float TO;
            if (tt == WINDOW - 1) {
                TO = s->Esm[r];
                s->tout[r][i] = TO;
                out[(size_t)(b0 + r) * T_LEN + i] = TO;
            } else {
                TO = s->tout[r][pos];
            }
            float e0 = enc ? fmaf(Xb[pos * 7], ratio, TO * (1.f - ratio)) : TO;
            s->xv[r][tt][0] = e0;
            #pragma unroll
            for (int j = 1; j < 5; ++j) s->xv[r][tt][j] = Xb[pos * 7 + j];
        }
        __syncthreads();

        // ---- 8 LSTM sub-steps ----
        #pragma unroll 1
        for (int st = 0; st < WINDOW; ++st) {
            ull a00 = 0, a01 = 0, a02 = 0, a03 = 0;
            ull a10 = 0, a11 = 0, a12 = 0, a13 = 0;
            const ulonglong2* hq0 = reinterpret_cast<const ulonglong2*>(s->h2[0]);
            const ulonglong2* hq1 = reinterpret_cast<const ulonglong2*>(s->h2[1]);
            const ulonglong2* hq2 = reinterpret_cast<const ulonglong2*>(s->h2[2]);
            const ulonglong2* hq3 = reinterpret_cast<const ulonglong2*>(s->h2[3]);
            // smem part: k-quads 0..19 (k 0..79)
            #pragma unroll 5
            for (int k4 = 0; k4 < K4_SM; ++k4) {
                ulonglong2 w0 = *reinterpret_cast<const ulonglong2*>(&s->Wq[k4][tid][0]);
                ulonglong2 w1 = *reinterpret_cast<const ulonglong2*>(&s->Wq[k4][tid + 256][0]);
                ulonglong2 h0 = hq0[k4], h1 = hq1[k4], h2 = hq2[k4], h3 = hq3[k4];
                a00 = ffma2(w0.x, h0.x, a00);  a00 = ffma2(w0.y, h0.y, a00);
                a10 = ffma2(w1.x, h0.x, a10);  a10 = ffma2(w1.y, h0.y, a10);
                a01 = ffma2(w0.x, h1.x, a01);  a01 = ffma2(w0.y, h1.y, a01);
                a11 = ffma2(w1.x, h1.x, a11);  a11 = ffma2(w1.y, h1.y, a11);
                a02 = ffma2(w0.x, h2.x, a02);  a02 = ffma2(w0.y, h2.y, a02);
                a12 = ffma2(w1.x, h2.x, a12);  a12 = ffma2(w1.y, h2.y, a12);
                a03 = ffma2(w0.x, h3.x, a03);  a03 = ffma2(w0.y, h3.y, a03);
                a13 = ffma2(w1.x, h3.x, a13);  a13 = ffma2(w1.y, h3.y, a13);
            }
            // register tail: FULLY UNROLLED so wt0/wt1 stay in registers
            #pragma unroll
            for (int q = 0; q < TAIL_P / 2; ++q) {
                ulonglong2 h0 = hq0[K4_SM + q], h1 = hq1[K4_SM + q];
                ulonglong2 h2 = hq2[K4_SM + q], h3 = hq3[K4_SM + q];
                ull wa0 = wt0[2*q], wb0 = wt0[2*q+1];
                ull wa1 = wt1[2*q], wb1 = wt1[2*q+1];
                a00 = ffma2(wa0, h0.x, a00);  a00 = ffma2(wb0, h0.y, a00);
                a10 = ffma2(wa1, h0.x, a10);  a10 = ffma2(wb1, h0.y, a10);
                a01 = ffma2(wa0, h1.x, a01);  a01 = ffma2(wb0, h1.y, a01);
                a11 = ffma2(wa1, h1.x, a11);  a11 = ffma2(wb1, h1.y, a11);
                a02 = ffma2(wa0, h2.x, a02);  a02 = ffma2(wb0, h2.y, a02);
                a12 = ffma2(wa1, h2.x, a12);  a12 = ffma2(wb1, h2.y, a12);
                a03 = ffma2(wa0, h3.x, a03);  a03 = ffma2(wb0, h3.y, a03);
                a13 = ffma2(wa1, h3.x, a13);  a13 = ffma2(wb1, h3.y, a13);
            }
            // x-part computed AFTER the dot (short live ranges)
            float init0[R_ROWS], init1[R_ROWS];
            #pragma unroll
            for (int r = 0; r < R_ROWS; ++r) {
                float v0 = btA, v1 = btB;
                #pragma unroll
                for (int j = 0; j < 5; ++j) {
                    float xj = s->xv[r][st][j];
                    v0 = fmaf(xj, wihA[j], v0);
                    v1 = fmaf(xj, wihB[j], v1);
                }
                init0[r] = v0; init1[r] = v1;
            }
            s->g[0][tid]       = init0[0] + lo32(a00) + hi32(a00);
            s->g[1][tid]       = init0[1] + lo32(a01) + hi32(a01);
            s->g[2][tid]       = init0[2] + lo32(a02) + hi32(a02);
            s->g[3][tid]       = init0[3] + lo32(a03) + hi32(a03);
            s->g[0][tid + 256] = init1[0] + lo32(a10) + hi32(a10);
            s->g[1][tid + 256] = init1[1] + lo32(a11) + hi32(a11);
            s->g[2][tid + 256] = init1[2] + lo32(a12) + hi32(a12);
            s->g[3][tid + 256] = init1[3] + lo32(a13) + hi32(a13);
            __syncthreads();

            // phase 2: c/h update — MUFU.TANH activations (short serial chain)
            {
                float* hf = reinterpret_cast<float*>(&s->h2[0][0]);
                {
                    int r = rA;
                    float gi = s->g[r][uu], gf = s->g[r][uu + 128];
                    float gg = s->g[r][uu + 256], go = s->g[r][uu + 384];
                    c0 = sigf(gf) * c0 + sigf(gi) * tanh_hw(gg);
                    hf[r * HID + uu] = sigf(go) * tanh_hw(c0);
                }
                {
                    int r = rA + 2;
                    float gi = s->g[r][uu], gf = s->g[r][uu + 128];
                    float gg = s->g[r][uu + 256], go = s->g[r][uu + 384];
                    c1 = sigf(gf) * c1 + sigf(gi) * tanh_hw(gg);
                    hf[r * HID + uu] = sigf(go) * tanh_hw(c1);
                }
            }
            __syncthreads();
        }

        // ---- ext head ----
        {
            const ull* hA = s->h2[rA];
            const ull* hB = s->h2[rA + 2];
            ull A0 = 0, A1 = 0;
            #pragma unroll 8
            for (int k2 = 0; k2 < 64; ++k2) {
                ull w = __ldg(&g_fc1p[k2 * HID + uu]);
                A0 = ffma2(w, hA[k2], A0);
                A1 = ffma2(w, hB[k2], A1);
            }
            float b1 = s->fc1b[uu], w2 = s->fc2w[uu];
            float p0 = fmaxf(lo32(A0) + hi32(A0) + b1, 0.f) * w2;
            float p1 = fmaxf(lo32(A1) + hi32(A1) + b1, 0.f) * w2;
            #pragma unroll
            for (int m = 16; m > 0; m >>= 1) {
                p0 += __shfl_xor_sync(0xFFFFFFFFu, p0, m);
                p1 += __shfl_xor_sync(0xFFFFFFFFu, p1, m);
            }
            if ((tid & 31) == 0) {
                int w8 = tid >> 5;
                s->red[rA][w8 & 3]     = p0;
                s->red[rA + 2][w8 & 3] = p1;
            }
        }
        __syncthreads();

        // ---- scalar tail ----
        if (tid < R_ROWS) {
            int r = tid;
            float dot = s->red[r][0] + s->red[r][1] + s->red[r][2] + s->red[r][3];
            float ext = dot + fcb2;
            const float* Xb = X + (size_t)(b0 + r) * (T_LEN * 7);
            float hv = Xb[i * 7 + 6];
            float it = s->intv[r][i];
            float total = ext + hv + it;
            out[2*(size_t)BT + (size_t)(b0 + r) * T_LEN + i] = ext;
            float E = s->Esm[r];
            if (enc) E = ratio * Xb[i * 7] + (1.f - ratio) * E + total * zone;
            else     E = total * zone + E;
            s->Esm[r] = E;
        }
        __syncthreads();
    }
}

extern "C" void kernel_launch(void* const* d_in, const int* in_sizes, int n_in,
                              void* d_out, int out_size) {
    const float* X       = (const float*)d_in[0];
    const float* W_ih    = (const float*)d_in[1];
    const float* W_hh    = (const float*)d_in[2];
    const float* b_ih    = (const float*)d_in[3];
    const float* b_hh    = (const float*)d_in[4];
    const float* fc1_w   = (const float*)d_in[5];
    const float* fc1_b   = (const float*)d_in[6];
    const float* fc2_w   = (const float*)d_in[7];
    const float* fc2_b   = (const float*)d_in[8];
    const float* int1_w  = (const float*)d_in[9];
    const float* int1_b  = (const float*)d_in[10];
    const float* int3_w  = (const float*)d_in[11];
    const float* int3_b  = (const float*)d_in[12];
    const float* scale_w = (const float*)d_in[13];
    const float* zone_w  = (const float*)d_in[14];
    float* out = (float*)d_out;

    prep_fc1<<<64, 128>>>(fc1_w);

    size_t smem = sizeof(Smem);
    cudaFuncSetAttribute(modnn_kernel, cudaFuncAttributeMaxDynamicSharedMemorySize, (int)smem);
    modnn_kernel<<<NCTA, NTHR, smem>>>(X, W_ih, W_hh, b_ih, b_hh,
                                       fc1_b, fc2_w, fc2_b,
                                       int1_w, int1_b, int3_w, int3_b,
                                       scale_w, zone_w, out);
}